// round 13
// baseline (speedup 1.0000x reference)
#include <cuda_runtime.h>
#include <cuda_bf16.h>
#include <cstdint>

#define BS 2
#define NN 512
#define DD 128
#define SZ (BS*NN*DD)   // 131072
#define KS 4            // K-splits in main tensor GEMM

// tcgen05 is arch-SPECIFIC; generic compute_103 PTX pass compiles fallbacks.
#if defined(__CUDA_ARCH_FEAT_SM103_ALL) || defined(__CUDA_ARCH_FEAT_SM100_ALL) || defined(__CUDA_ARCH_FEAT_SM101_ALL)
#define HAS_TC 1
#else
#define HAS_TC 0
#endif

typedef unsigned long long u64;

// ---------------- device scratch ----------------
__device__ float g_sq[SZ];                    // sigmoid(q)
__device__ __nv_bfloat16 g_xh[SZ], g_xl[SZ];  // x hi/lo
__device__ __nv_bfloat16 g_wh[3*DD*DD];       // W^T hi: [mat][n][k]  (q,k,v)
__device__ __nv_bfloat16 g_wl[3*DD*DD];       // W^T lo
__device__ __nv_bfloat16 g_ah[NN*NN], g_al[NN*NN];      // eB hi/lo
__device__ __nv_bfloat16 g_bh[BS*256*NN], g_bl[BS*256*NN]; // [b][n][j]: n<128 ev^T, else ek^T
__device__ float g_part[KS*BS*NN*256];        // MMA partials [ks][b][i][256]

// ---------------- helpers ----------------
__device__ __forceinline__ u64 pack2(float lo, float hi) {
    u64 r; asm("mov.b64 %0, {%1, %2};" : "=l"(r) : "f"(lo), "f"(hi)); return r;
}
__device__ __forceinline__ void cp16(void* sdst, const void* gsrc) {
    unsigned s = (unsigned)__cvta_generic_to_shared(sdst);
    asm volatile("cp.async.ca.shared.global [%0], [%1], 16;" :: "r"(s), "l"(gsrc));
}
__device__ __forceinline__ void cp_commit() { asm volatile("cp.async.commit_group;"); }
template<int NPEND> __device__ __forceinline__ void cp_wait() {
    asm volatile("cp.async.wait_group %0;" :: "n"(NPEND));
}
__device__ __forceinline__ uint32_t smem_u32(const void* p) {
    return (uint32_t)__cvta_generic_to_shared(p);
}
__device__ __forceinline__ void bf16_split(float v, __nv_bfloat16& h, __nv_bfloat16& l) {
    h = __float2bfloat16(v);
    l = __float2bfloat16(v - __bfloat162float(h));
}

#if HAS_TC
__device__ __forceinline__ uint32_t elect_one_pred() {
    uint32_t pred;
    asm volatile("{\n\t.reg .pred p;\n\telect.sync _|p, 0xFFFFFFFF;\n\t"
                 "selp.b32 %0, 1, 0, p;\n\t}" : "=r"(pred));
    return pred;
}
static constexpr u64 DESC_BASE_SW128 =
    (u64(2) << 61) | (u64(1) << 46) | (u64(64) << 32) | (u64(1) << 16);
__device__ __forceinline__ u64 make_desc(uint32_t addr) {
    return DESC_BASE_SW128 | ((u64)(addr >> 4) & 0x3FFF);
}
__device__ __forceinline__ void mma_f16_ss(uint32_t d_tmem, u64 a_desc, u64 b_desc,
                                           uint32_t idesc, uint32_t en) {
    asm volatile(
        "{\n\t.reg .pred p;\n\tsetp.ne.u32 p, %5, 0;\n\t"
        "tcgen05.mma.cta_group::1.kind::f16 [%0], %1, %2, %3, {%4, %4, %4, %4}, p;\n\t}"
        :: "r"(d_tmem), "l"(a_desc), "l"(b_desc), "r"(idesc), "r"(0u), "r"(en)
        : "memory");
}
__device__ __forceinline__ uint32_t idesc_f16(int N) {
    return (1u << 4) | (1u << 7) | (1u << 10) | ((uint32_t)(N/8) << 17) | (8u << 24);
}
#define TMEM_ALLOC(sb, n) \
    asm volatile("tcgen05.alloc.cta_group::1.sync.aligned.shared::cta.b32 [%0], %1;" \
                 :: "r"(sb), "r"((uint32_t)(n)) : "memory")
#define TMEM_LD32(r, addr) \
    asm volatile( \
        "tcgen05.ld.sync.aligned.32x32b.x32.b32 " \
        "{%0, %1, %2, %3, %4, %5, %6, %7, %8, %9, %10, %11, %12, %13, %14, %15, " \
        " %16, %17, %18, %19, %20, %21, %22, %23, %24, %25, %26, %27, %28, %29, %30, %31}, [%32];" \
        : "=r"((r)[0]), "=r"((r)[1]), "=r"((r)[2]), "=r"((r)[3]), "=r"((r)[4]), "=r"((r)[5]), \
          "=r"((r)[6]), "=r"((r)[7]), "=r"((r)[8]), "=r"((r)[9]), "=r"((r)[10]), "=r"((r)[11]), \
          "=r"((r)[12]), "=r"((r)[13]), "=r"((r)[14]), "=r"((r)[15]), "=r"((r)[16]), "=r"((r)[17]), \
          "=r"((r)[18]), "=r"((r)[19]), "=r"((r)[20]), "=r"((r)[21]), "=r"((r)[22]), "=r"((r)[23]), \
          "=r"((r)[24]), "=r"((r)[25]), "=r"((r)[26]), "=r"((r)[27]), "=r"((r)[28]), "=r"((r)[29]), \
          "=r"((r)[30]), "=r"((r)[31]) : "r"(addr))
#define TMEM_WAIT_LD() asm volatile("tcgen05.wait::ld.sync.aligned;" ::: "memory")
#define MBAR_WAIT0(addr) do { \
    uint32_t _done; \
    asm volatile("{\n\t.reg .pred p;\n\t" \
        "mbarrier.try_wait.parity.acquire.cta.shared::cta.b64 p, [%1], 0;\n\t" \
        "selp.b32 %0, 1, 0, p;\n\t}" : "=r"(_done) : "r"(addr) : "memory"); \
    if (!_done) { \
        asm volatile("{\n\t.reg .pred P1;\n\t" \
            "WL_%=:\n\t" \
            "mbarrier.try_wait.parity.acquire.cta.shared::cta.b64 P1, [%0], 0, 0x989680;\n\t" \
            "@P1 bra.uni WD_%=;\n\tbra.uni WL_%=;\n\tWD_%=:\n\t}" \
            :: "r"(addr) : "memory"); \
    } } while (0)
#endif

// ---------------- K0: prep (eB split, x split, W transpose+split) ----------------
// grid (64, 2), 256 threads.
//   y=0:           eB = exp(B) -> bf16 hi/lo
//   y=1, bx<32:    x -> bf16 hi/lo
//   y=1, 32<=bx<44: W transpose+split: t=bx-32, mat=t>>2, k0=(t&3)*32
__global__ __launch_bounds__(256) void prep_kernel(
    const float* __restrict__ x,
    const float* __restrict__ Wq, const float* __restrict__ Wk,
    const float* __restrict__ Wv, const float* __restrict__ Bm)
{
    const int tid = threadIdx.x;
    if (blockIdx.y == 0) {
        #pragma unroll
        for (int r = 0; r < 4; ++r) {
            const int off = blockIdx.x * 4096 + r * 1024 + tid * 4;
            const float4 b4 = *(const float4*)&Bm[off];
            float e[4] = {__expf(b4.x), __expf(b4.y), __expf(b4.z), __expf(b4.w)};
            __nv_bfloat16 h[4], l[4];
            #pragma unroll
            for (int t = 0; t < 4; ++t) bf16_split(e[t], h[t], l[t]);
            *(uint2*)&g_ah[off] = *(uint2*)h;
            *(uint2*)&g_al[off] = *(uint2*)l;
        }
        return;
    }
    if (blockIdx.x < 32) {   // x split
        #pragma unroll
        for (int r = 0; r < 4; ++r) {
            const int off = blockIdx.x * 4096 + r * 1024 + tid * 4;
            const float4 xv = *(const float4*)&x[off];
            __nv_bfloat16 h[4], l[4];
            bf16_split(xv.x, h[0], l[0]); bf16_split(xv.y, h[1], l[1]);
            bf16_split(xv.z, h[2], l[2]); bf16_split(xv.w, h[3], l[3]);
            *(uint2*)&g_xh[off] = *(uint2*)h;
            *(uint2*)&g_xl[off] = *(uint2*)l;
        }
        return;
    }
    const int t = blockIdx.x - 32;
    if (t >= 12) return;
    const int m = t >> 2, k0 = (t & 3) * 32;
    const float* W = (m == 0) ? Wq : ((m == 1) ? Wk : Wv);
    __shared__ float ws[32][132];
    #pragma unroll
    for (int q = 0; q < 16; ++q) {
        const int e = tid + q * 256;
        const int kk = e >> 7, n = e & 127;
        ws[kk][n] = W[(k0 + kk) * 128 + n];
    }
    __syncthreads();
    const int n = tid >> 1, half = tid & 1;
    const int kb = half * 16;
    #pragma unroll
    for (int s = 0; s < 16; ++s) {
        __nv_bfloat16 h, l;
        bf16_split(ws[kb + s][n], h, l);
        const int off = m * 16384 + n * 128 + k0 + kb + s;
        g_wh[off] = h; g_wl[off] = l;
    }
}

// ---------------- K1: proj_tc — q/k/v GEMMs on tcgen05, fused epilogue ----------------
// grid (8, 2), 128 threads. chain 0: q (N=128) -> sigmoid -> g_sq.
// chain 1: [k|v] (N=256) -> ek=exp(k+bk), ev=ek*(v+bv) -> bf16 hi/lo transposed g_bh/g_bl.
#define PA_H 1024
#define PA_L (PA_H + 32768)
#define PB_H (PA_L + 32768)
#define PB_L (PB_H + 65536)
#define PR_TOTAL (PB_L + 65536)

__global__ __launch_bounds__(128) void proj_tc_kernel(
    const float* __restrict__ bq, const float* __restrict__ bk,
    const float* __restrict__ bv)
{
    extern __shared__ char smem[];
    const int tid = threadIdx.x;
    const int wid = tid >> 5, lane = tid & 31;
    const int chain = blockIdx.y;
    const int NR = chain ? 256 : 128;
    const int nbase = chain ? 128 : 0;
    const int it0 = blockIdx.x * 128;
    const int r = it0 + wid * 32 + lane;     // global fused row
    const int b = r >> 9, j = r & 511;

#if HAS_TC
    const uint32_t sbase = smem_u32(smem);
    if (wid == 0) TMEM_ALLOC(sbase, 256u);
    if (tid == 0)
        asm volatile("mbarrier.init.shared.b64 [%0], 1;" :: "r"(sbase + 8) : "memory");

    // stage A = x tile hi/lo [128 rows][128 k], SW128, 2 k-sub-tiles
    #pragma unroll
    for (int m = 0; m < 2; ++m) {
        const int abase = m ? PA_L : PA_H;
        const __nv_bfloat16* src = m ? g_xl : g_xh;
        #pragma unroll
        for (int sub = 0; sub < 2; ++sub)
            #pragma unroll
            for (int q = 0; q < 8; ++q) {
                const int e = tid + q * 128;
                const int row = e >> 3, u = e & 7;
                cp16(smem + abase + sub * 16384 + row * 128 + ((u ^ (row & 7)) * 16),
                     &src[(it0 + row) * 128 + sub * 64 + u * 8]);
            }
    }
    // stage B = W^T hi/lo [NR rows][128 k]
    const int nq = NR / 16;   // 8 or 16
    #pragma unroll
    for (int m = 0; m < 2; ++m) {
        const int bbase = m ? PB_L : PB_H;
        const __nv_bfloat16* src = m ? g_wl : g_wh;
        for (int sub = 0; sub < 2; ++sub)
            for (int q = 0; q < nq; ++q) {
                const int e = tid + q * 128;
                const int row = e >> 3, u = e & 7;
                cp16(smem + bbase + sub * (NR * 128) + row * 128 + ((u ^ (row & 7)) * 16),
                     &src[(nbase + row) * 128 + sub * 64 + u * 8]);
            }
    }
    cp_commit();
    cp_wait<0>();
    __syncthreads();
    asm volatile("fence.proxy.async.shared::cta;" ::: "memory");

    uint32_t tmem;
    asm volatile("ld.shared.b32 %0, [%1];" : "=r"(tmem) : "r"(sbase));

    if (wid == 0 && elect_one_pred()) {
        const u64 adh = make_desc(sbase + PA_H), adl = make_desc(sbase + PA_L);
        const u64 bdh = make_desc(sbase + PB_H), bdl = make_desc(sbase + PB_L);
        const u64 ad[3] = {adh, adh, adl};
        const u64 bd[3] = {bdh, bdl, bdh};
        const uint32_t idesc = idesc_f16(NR);
        const int bsub = NR * 8;   // desc units per B sub-tile
        int first = 1;
        #pragma unroll
        for (int sp = 0; sp < 3; ++sp)
            #pragma unroll
            for (int sub = 0; sub < 2; ++sub)
                #pragma unroll
                for (int ks = 0; ks < 4; ++ks) {
                    mma_f16_ss(tmem, ad[sp] + sub * 1024 + ks * 2,
                               bd[sp] + sub * bsub + ks * 2, idesc, first ? 0u : 1u);
                    first = 0;
                }
        asm volatile(
            "tcgen05.commit.cta_group::1.mbarrier::arrive::one.shared::cluster.b64 [%0];"
            :: "r"(sbase + 8) : "memory");
    }
    __syncthreads();
    MBAR_WAIT0(sbase + 8);
    asm volatile("tcgen05.fence::after_thread_sync;" ::: "memory");

    if (chain == 0) {
        for (int cb = 0; cb < 128; cb += 32) {
            uint32_t q32[32];
            TMEM_LD32(q32, tmem + cb);
            TMEM_WAIT_LD();
            #pragma unroll
            for (int t = 0; t < 32; ++t) {
                const float qv = __uint_as_float(q32[t]) + bq[cb + t];
                g_sq[r * 128 + cb + t] = 1.f / (1.f + __expf(-qv));
            }
        }
    } else {
        for (int cb = 0; cb < 128; cb += 32) {
            uint32_t k32[32], v32[32];
            TMEM_LD32(k32, tmem + cb);
            TMEM_LD32(v32, tmem + 128 + cb);
            TMEM_WAIT_LD();
            #pragma unroll
            for (int t = 0; t < 32; ++t) {
                const float kv = __uint_as_float(k32[t]) + bk[cb + t];
                const float vv = __uint_as_float(v32[t]) + bv[cb + t];
                const float ek = __expf(kv);
                const float ev = ek * vv;
                __nv_bfloat16 ekh, ekl, evh, evl;
                bf16_split(ek, ekh, ekl);
                bf16_split(ev, evh, evl);
                const int ov = b * 256 * NN + (cb + t) * NN + j;
                const int ok = b * 256 * NN + (128 + cb + t) * NN + j;
                g_bh[ov] = evh; g_bl[ov] = evl;
                g_bh[ok] = ekh; g_bl[ok] = ekl;
            }
        }
    }

    __syncthreads();
    if (tid == 0)
        asm volatile("mbarrier.inval.shared.b64 [%0];" :: "r"(sbase + 8) : "memory");
    __syncthreads();
    if (wid == 0) {
        asm volatile("tcgen05.relinquish_alloc_permit.cta_group::1.sync.aligned;");
        asm volatile("tcgen05.dealloc.cta_group::1.sync.aligned.b32 %0, %1;"
                     :: "r"(tmem), "r"(256u));
    }
#else
    // Generic-PTX fallback (never selected on GB300). Correct scalar path.
    (void)smem;
    const int i = it0 + tid;   // 128 threads: one fused row each
    if (chain == 0) {
        for (int n = 0; n < 128; ++n) {
            float acc = bq[n];
            for (int k = 0; k < 128; ++k) {
                const float xr = __bfloat162float(g_xh[i*128 + k]) + __bfloat162float(g_xl[i*128 + k]);
                const float wr = __bfloat162float(g_wh[n*128 + k]) + __bfloat162float(g_wl[n*128 + k]);
                acc += xr * wr;
            }
            g_sq[i*128 + n] = 1.f / (1.f + __expf(-acc));
        }
    } else {
        const int bb = i >> 9, jj = i & 511;
        float karr[128];
        for (int n = 0; n < 128; ++n) {
            float acc = bk[n];
            for (int k = 0; k < 128; ++k) {
                const float xr = __bfloat162float(g_xh[i*128 + k]) + __bfloat162float(g_xl[i*128 + k]);
                const float wr = __bfloat162float(g_wh[(128+n)*128 + k]) + __bfloat162float(g_wl[(128+n)*128 + k]);
                acc += xr * wr;
            }
            karr[n] = __expf(acc);
        }
        for (int n = 0; n < 128; ++n) {
            float acc = bv[n];
            for (int k = 0; k < 128; ++k) {
                const float xr = __bfloat162float(g_xh[i*128 + k]) + __bfloat162float(g_xl[i*128 + k]);
                const float wr = __bfloat162float(g_wh[(256+n)*128 + k]) + __bfloat162float(g_wl[(256+n)*128 + k]);
                acc += xr * wr;
            }
            const float ek = karr[n], ev = ek * acc;
            __nv_bfloat16 ekh, ekl, evh, evl;
            bf16_split(ek, ekh, ekl); bf16_split(ev, evh, evl);
            const int ov = bb*256*NN + n*NN + jj, ok = bb*256*NN + (128+n)*NN + jj;
            g_bh[ov] = evh; g_bl[ov] = evl;
            g_bh[ok] = ekh; g_bl[ok] = ekl;
        }
    }
#endif
}

// ---------------- K2: tcgen05 GEMM  part = eB @ [ev|ek]  (bf16-split x3) ----------------
#define SM_AH 1024
#define SM_AL (SM_AH + 32768)
#define SM_BH (SM_AL + 32768)
#define SM_BL (SM_BH + 65536)
#define SM_TOTAL (SM_BL + 65536 + 1024)

__global__ __launch_bounds__(128) void aft_tc_kernel()
{
    extern __shared__ char smem[];
    const int tid = threadIdx.x;
    const int wid = tid >> 5, lane = tid & 31;
    const int it0 = blockIdx.x * 128;
    const int kb  = blockIdx.y * 128;
    const int b   = blockIdx.z;

#if HAS_TC
    const uint32_t sbase = smem_u32(smem);
    if (wid == 0) TMEM_ALLOC(sbase, 256u);
    if (tid == 0)
        asm volatile("mbarrier.init.shared.b64 [%0], 1;" :: "r"(sbase + 8) : "memory");

    {
        const __nv_bfloat16* asrc[2] = {g_ah, g_al};
        #pragma unroll
        for (int m = 0; m < 2; ++m) {
            const int abase = m ? SM_AL : SM_AH;
            #pragma unroll
            for (int sub = 0; sub < 2; ++sub)
                #pragma unroll
                for (int q = 0; q < 8; ++q) {
                    const int e = tid + q*128;
                    const int row = e >> 3, u = e & 7;
                    cp16(smem + abase + sub*16384 + row*128 + ((u ^ (row & 7)) * 16),
                         &asrc[m][(it0 + row)*NN + kb + sub*64 + u*8]);
                }
        }
        const __nv_bfloat16* bsrc[2] = {g_bh, g_bl};
        #pragma unroll
        for (int m = 0; m < 2; ++m) {
            const int bbase = m ? SM_BL : SM_BH;
            #pragma unroll
            for (int sub = 0; sub < 2; ++sub)
                #pragma unroll
                for (int q = 0; q < 16; ++q) {
                    const int e = tid + q*128;
                    const int row = e >> 3, u = e & 7;
                    cp16(smem + bbase + sub*32768 + row*128 + ((u ^ (row & 7)) * 16),
                         &bsrc[m][b*256*NN + row*NN + kb + sub*64 + u*8]);
                }
        }
    }
    cp_commit();
    cp_wait<0>();
    __syncthreads();
    asm volatile("fence.proxy.async.shared::cta;" ::: "memory");

    uint32_t tmem;
    asm volatile("ld.shared.b32 %0, [%1];" : "=r"(tmem) : "r"(sbase));

    if (wid == 0 && elect_one_pred()) {
        const u64 adh = make_desc(sbase + SM_AH), adl = make_desc(sbase + SM_AL);
        const u64 bdh = make_desc(sbase + SM_BH), bdl = make_desc(sbase + SM_BL);
        const u64 ad[3] = {adh, adh, adl};
        const u64 bd[3] = {bdh, bdl, bdh};
        const uint32_t idesc = idesc_f16(256);
        int first = 1;
        #pragma unroll
        for (int sp = 0; sp < 3; ++sp)
            #pragma unroll
            for (int sub = 0; sub < 2; ++sub)
                #pragma unroll
                for (int ks = 0; ks < 4; ++ks) {
                    mma_f16_ss(tmem, ad[sp] + sub*1024 + ks*2,
                               bd[sp] + sub*2048 + ks*2, idesc, first ? 0u : 1u);
                    first = 0;
                }
        asm volatile(
            "tcgen05.commit.cta_group::1.mbarrier::arrive::one.shared::cluster.b64 [%0];"
            :: "r"(sbase + 8) : "memory");
    }
    __syncthreads();
    MBAR_WAIT0(sbase + 8);
    asm volatile("tcgen05.fence::after_thread_sync;" ::: "memory");

    float* dst = &g_part[(((size_t)blockIdx.y*BS + b)*NN + it0 + wid*32 + lane) * 256];
    for (int cb = 0; cb < 256; cb += 32) {
        uint32_t rg[32];
        TMEM_LD32(rg, tmem + cb);
        TMEM_WAIT_LD();
        #pragma unroll
        for (int t = 0; t < 8; ++t)
            *(float4*)&dst[cb + t*4] = make_float4(
                __uint_as_float(rg[t*4+0]), __uint_as_float(rg[t*4+1]),
                __uint_as_float(rg[t*4+2]), __uint_as_float(rg[t*4+3]));
    }

    __syncthreads();
    if (tid == 0)
        asm volatile("mbarrier.inval.shared.b64 [%0];" :: "r"(sbase + 8) : "memory");
    __syncthreads();
    if (wid == 0) {
        asm volatile("tcgen05.relinquish_alloc_permit.cta_group::1.sync.aligned;");
        asm volatile("tcgen05.dealloc.cta_group::1.sync.aligned.b32 %0, %1;"
                     :: "r"(tmem), "r"(256u));
    }
#else
    (void)smem; (void)wid; (void)lane;
    const int i = it0 + tid;
    float* dst = &g_part[(((size_t)blockIdx.y*BS + b)*NN + i) * 256];
    for (int n = 0; n < 256; ++n) {
        float acc = 0.f;
        for (int jj = 0; jj < 128; ++jj) {
            const float a = __bfloat162float(g_ah[i*NN + kb + jj])
                          + __bfloat162float(g_al[i*NN + kb + jj]);
            const float bb = __bfloat162float(g_bh[b*256*NN + n*NN + kb + jj])
                           + __bfloat162float(g_bl[b*256*NN + n*NN + kb + jj]);
            acc += a * bb;
        }
        dst[n] = acc;
    }
#endif
}

// ---------------- K3: reduce K-split partials + epilogue ----------------
__global__ __launch_bounds__(256) void reduce_kernel(float* __restrict__ out)
{
    const int idx4 = (blockIdx.x * 256 + threadIdx.x) * 4;
    const int b = idx4 >> 16;
    const int i = (idx4 >> 7) & (NN - 1);
    const int d = idx4 & (DD - 1);

    float4 n = make_float4(0.f, 0.f, 0.f, 0.f);
    float4 dn = make_float4(0.f, 0.f, 0.f, 0.f);
    #pragma unroll
    for (int ks = 0; ks < KS; ++ks) {
        const float* base = &g_part[(((size_t)ks*BS + b)*NN + i) * 256];
        const float4 a = *(const float4*)&base[d];
        const float4 c = *(const float4*)&base[128 + d];
        n.x += a.x; n.y += a.y; n.z += a.z; n.w += a.w;
        dn.x += c.x; dn.y += c.y; dn.z += c.z; dn.w += c.w;
    }
    const float4 sq = *(const float4*)&g_sq[idx4];
    float4 o;
    o.x = sq.x * __fdividef(n.x, dn.x);
    o.y = sq.y * __fdividef(n.y, dn.y);
    o.z = sq.z * __fdividef(n.z, dn.z);
    o.w = sq.w * __fdividef(n.w, dn.w);
    *(float4*)&out[idx4] = o;
}

// ---------------- launch ----------------
extern "C" void kernel_launch(void* const* d_in, const int* in_sizes, int n_in,
                              void* d_out, int out_size)
{
    const float* x  = (const float*)d_in[0];
    const float* Wq = (const float*)d_in[1];
    const float* bq = (const float*)d_in[2];
    const float* Wk = (const float*)d_in[3];
    const float* bk = (const float*)d_in[4];
    const float* Wv = (const float*)d_in[5];
    const float* bv = (const float*)d_in[6];
    const float* B  = (const float*)d_in[7];
    float* out = (float*)d_out;

    cudaFuncSetAttribute(proj_tc_kernel, cudaFuncAttributeMaxDynamicSharedMemorySize, PR_TOTAL);
    cudaFuncSetAttribute(aft_tc_kernel,  cudaFuncAttributeMaxDynamicSharedMemorySize, SM_TOTAL);

    prep_kernel<<<dim3(64, 2), 256>>>(x, Wq, Wk, Wv, B);
    proj_tc_kernel<<<dim3(8, 2), 128, PR_TOTAL>>>(bq, bk, bv);
    aft_tc_kernel<<<dim3(4, KS, BS), 128, SM_TOTAL>>>();
    reduce_kernel<<<SZ/4/256, 256>>>(out);
}

// round 14
// speedup vs baseline: 1.5240x; 1.5240x over previous
#include <cuda_runtime.h>
#include <cuda_bf16.h>
#include <cstdint>

#define BS 2
#define NN 512
#define DD 128
#define SZ (BS*NN*DD)   // 131072
#define KS 4            // K-splits in tensor GEMM

#if defined(__CUDA_ARCH_FEAT_SM103_ALL) || defined(__CUDA_ARCH_FEAT_SM100_ALL) || defined(__CUDA_ARCH_FEAT_SM101_ALL)
#define HAS_TC 1
#else
#define HAS_TC 0
#endif

typedef unsigned long long u64;

// ---------------- device scratch ----------------
__device__ float g_sq[SZ];                    // sigmoid(q)
__device__ float g_ek[SZ];                    // exp(k) f32
__device__ float g_v [SZ];                    // raw v f32
__device__ __nv_bfloat16 g_ah[NN*NN];         // eB hi
__device__ __nv_bfloat16 g_al[NN*NN];         // eB lo
__device__ __nv_bfloat16 g_bh[BS*256*NN];     // [b][n][j]: n<128 ev^T, n>=128 ek^T (hi)
__device__ __nv_bfloat16 g_bl[BS*256*NN];     // lo
__device__ float g_part[KS*BS*NN*256];        // MMA partials [ks][b][i][256]

// ---------------- helpers ----------------
__device__ __forceinline__ u64 pack2(float lo, float hi) {
    u64 r; asm("mov.b64 %0, {%1, %2};" : "=l"(r) : "f"(lo), "f"(hi)); return r;
}
__device__ __forceinline__ void ffma2(u64 &acc, u64 a, u64 b) {
    asm("fma.rn.f32x2 %0, %1, %2, %0;" : "+l"(acc) : "l"(a), "l"(b));
}
__device__ __forceinline__ float2 unpack2(u64 v) {
    float lo, hi; asm("mov.b64 {%0, %1}, %2;" : "=f"(lo), "=f"(hi) : "l"(v));
    return make_float2(lo, hi);
}
__device__ __forceinline__ void cp16(void* sdst, const void* gsrc) {
    unsigned s = (unsigned)__cvta_generic_to_shared(sdst);
    asm volatile("cp.async.ca.shared.global [%0], [%1], 16;" :: "r"(s), "l"(gsrc));
}
__device__ __forceinline__ void cp_commit() { asm volatile("cp.async.commit_group;"); }
template<int NPEND> __device__ __forceinline__ void cp_wait() {
    asm volatile("cp.async.wait_group %0;" :: "n"(NPEND));
}
__device__ __forceinline__ uint32_t smem_u32(const void* p) {
    return (uint32_t)__cvta_generic_to_shared(p);
}
__device__ __forceinline__ void bf16_split(float v, __nv_bfloat16& h, __nv_bfloat16& l) {
    h = __float2bfloat16(v);
    l = __float2bfloat16(v - __bfloat162float(h));
}

#if HAS_TC
__device__ __forceinline__ uint32_t elect_one_pred() {
    uint32_t pred;
    asm volatile("{\n\t.reg .pred p;\n\telect.sync _|p, 0xFFFFFFFF;\n\t"
                 "selp.b32 %0, 1, 0, p;\n\t}" : "=r"(pred));
    return pred;
}
static constexpr u64 DESC_BASE_SW128 =
    (u64(2) << 61) | (u64(1) << 46) | (u64(64) << 32) | (u64(1) << 16);
__device__ __forceinline__ u64 make_desc(uint32_t addr) {
    return DESC_BASE_SW128 | ((u64)(addr >> 4) & 0x3FFF);
}
__device__ __forceinline__ void mma_f16_ss(uint32_t d_tmem, u64 a_desc, u64 b_desc,
                                           uint32_t idesc, uint32_t en) {
    asm volatile(
        "{\n\t.reg .pred p;\n\tsetp.ne.u32 p, %5, 0;\n\t"
        "tcgen05.mma.cta_group::1.kind::f16 [%0], %1, %2, %3, {%4, %4, %4, %4}, p;\n\t}"
        :: "r"(d_tmem), "l"(a_desc), "l"(b_desc), "r"(idesc), "r"(0u), "r"(en)
        : "memory");
}
static constexpr uint32_t MMA_IDESC =
    (1u << 4) | (1u << 7) | (1u << 10) | ((256u/8) << 17) | ((128u/16) << 24);
#define TMEM_LD32(r, addr) \
    asm volatile( \
        "tcgen05.ld.sync.aligned.32x32b.x32.b32 " \
        "{%0, %1, %2, %3, %4, %5, %6, %7, %8, %9, %10, %11, %12, %13, %14, %15, " \
        " %16, %17, %18, %19, %20, %21, %22, %23, %24, %25, %26, %27, %28, %29, %30, %31}, [%32];" \
        : "=r"((r)[0]), "=r"((r)[1]), "=r"((r)[2]), "=r"((r)[3]), "=r"((r)[4]), "=r"((r)[5]), \
          "=r"((r)[6]), "=r"((r)[7]), "=r"((r)[8]), "=r"((r)[9]), "=r"((r)[10]), "=r"((r)[11]), \
          "=r"((r)[12]), "=r"((r)[13]), "=r"((r)[14]), "=r"((r)[15]), "=r"((r)[16]), "=r"((r)[17]), \
          "=r"((r)[18]), "=r"((r)[19]), "=r"((r)[20]), "=r"((r)[21]), "=r"((r)[22]), "=r"((r)[23]), \
          "=r"((r)[24]), "=r"((r)[25]), "=r"((r)[26]), "=r"((r)[27]), "=r"((r)[28]), "=r"((r)[29]), \
          "=r"((r)[30]), "=r"((r)[31]) : "r"(addr))
#endif

// ---------------- K1: q/k/v projections + eB, single-stage smem ----------------
// grid (64, 4), 256 threads, 72KB dyn smem: xs[16*128] + Ws[128*128].
// Stage ALL of x-tile and W once (one barrier), then 128 uninterrupted c-steps.
__global__ __launch_bounds__(256) void proj_kernel(
    const float* __restrict__ x,
    const float* __restrict__ Wq, const float* __restrict__ bq,
    const float* __restrict__ Wk, const float* __restrict__ bk,
    const float* __restrict__ Wv, const float* __restrict__ bv,
    const float* __restrict__ Bm)
{
    extern __shared__ float sm[];
    float* xs = sm;              // 16*128
    float* Ws = sm + 2048;       // 128*128
    const int mat = blockIdx.y;
    const int tid = threadIdx.x;

    if (mat == 3) {   // eB -> bf16 hi/lo
        #pragma unroll
        for (int r = 0; r < 4; ++r) {
            const int off = blockIdx.x * 4096 + r * 1024 + tid * 4;
            const float4 b4 = *(const float4*)&Bm[off];
            float e[4] = {__expf(b4.x), __expf(b4.y), __expf(b4.z), __expf(b4.w)};
            __nv_bfloat16 h[4], l[4];
            #pragma unroll
            for (int t = 0; t < 4; ++t) bf16_split(e[t], h[t], l[t]);
            *(uint2*)&g_ah[off] = *(uint2*)h;
            *(uint2*)&g_al[off] = *(uint2*)l;
        }
        return;
    }

    const float* W    = (mat==0) ? Wq : ((mat==1) ? Wk : Wv);
    const float* bias = (mat==0) ? bq : ((mat==1) ? bk : bv);
    const int row0 = blockIdx.x * 16;
    const int dt = tid & 31, rt = tid >> 5;
    const int d = dt * 4;

    // one-shot staging: x (512 cp16) + all of W (4096 cp16)
    #pragma unroll
    for (int q = 0; q < 2; ++q) {
        const int e = tid + q*256;
        cp16(&xs[e*4], &x[row0*128 + e*4]);
    }
    #pragma unroll
    for (int q = 0; q < 16; ++q) {
        const int e = tid + q*256;
        cp16(&Ws[e*4], &W[e*4]);
    }
    cp_commit();
    cp_wait<0>();
    __syncthreads();

    const float4 bb = *(const float4*)&bias[d];
    u64 a00 = pack2(bb.x, bb.y), a01 = pack2(bb.z, bb.w);
    u64 a10 = a00, a11 = a01;

    #pragma unroll 8
    for (int c = 0; c < 128; ++c) {
        const u64* wrow = (const u64*)&Ws[c*128 + d];
        const u64 w01 = wrow[0], w23 = wrow[1];
        const float x0 = xs[rt*128 + c];
        const float x1 = xs[(rt+8)*128 + c];
        const u64 X0 = pack2(x0, x0), X1 = pack2(x1, x1);
        ffma2(a00, X0, w01); ffma2(a01, X0, w23);
        ffma2(a10, X1, w01); ffma2(a11, X1, w23);
    }

    #pragma unroll
    for (int r = 0; r < 2; ++r) {
        const int grow = row0 + ((r == 0) ? rt : (rt + 8));
        const float2 p = unpack2(r ? a10 : a00);
        const float2 q2 = unpack2(r ? a11 : a01);
        float4 o = make_float4(p.x, p.y, q2.x, q2.y);
        if (mat == 0) {
            o.x = 1.f/(1.f+__expf(-o.x)); o.y = 1.f/(1.f+__expf(-o.y));
            o.z = 1.f/(1.f+__expf(-o.z)); o.w = 1.f/(1.f+__expf(-o.w));
            *(float4*)&g_sq[grow*128 + d] = o;
        } else if (mat == 1) {
            o.x = __expf(o.x); o.y = __expf(o.y);
            o.z = __expf(o.z); o.w = __expf(o.w);
            *(float4*)&g_ek[grow*128 + d] = o;
        } else {
            *(float4*)&g_v[grow*128 + d] = o;
        }
    }
}

// ---------------- K2: transpose + bf16 hi/lo split of ek / ev ----------------
// grid (16, 4, 2): 32-j tile, 32-d tile, batch. 256 threads.
__global__ __launch_bounds__(256) void convert_kernel()
{
    __shared__ float ekS[32][33], vS[32][33];
    const int j0 = blockIdx.x * 32;
    const int d0 = blockIdx.y * 32;
    const int b  = blockIdx.z;
    const int tid = threadIdx.x;
    const int lane = tid & 31, rw = tid >> 5;

    #pragma unroll
    for (int p = 0; p < 4; ++p) {
        const int r = rw + p*8;
        ekS[r][lane] = g_ek[(b*NN + j0 + r)*DD + d0 + lane];
        vS [r][lane] = g_v [(b*NN + j0 + r)*DD + d0 + lane];
    }
    __syncthreads();

    #pragma unroll
    for (int p = 0; p < 4; ++p) {
        const int r = rw + p*8;
        const float ek = ekS[lane][r];
        const float ev = ek * vS[lane][r];
        __nv_bfloat16 evh, evl, ekh, ekl;
        bf16_split(ev, evh, evl);
        bf16_split(ek, ekh, ekl);
        const int offv = b*256*NN + (d0 + r)*NN + j0 + lane;
        const int offk = b*256*NN + (128 + d0 + r)*NN + j0 + lane;
        g_bh[offv] = evh; g_bl[offv] = evl;
        g_bh[offk] = ekh; g_bl[offk] = ekl;
    }
}

// ---------------- K3: tcgen05 GEMM  part = eB @ [ev|ek]  (bf16-split x3) ----------------
// grid (4 Mtile, 4 Ksplit, 2 b), 256 threads, ~194KB dyn smem.
#define SM_AH 1024
#define SM_AL (SM_AH + 32768)
#define SM_BH (SM_AL + 32768)
#define SM_BL (SM_BH + 65536)
#define SM_TOTAL (SM_BL + 65536 + 1024)

__global__ __launch_bounds__(256) void aft_tc_kernel()
{
    extern __shared__ char smem[];
    const int tid = threadIdx.x;
    const int wid = tid >> 5, lane = tid & 31;
    const int it0 = blockIdx.x * 128;
    const int kb  = blockIdx.y * 128;
    const int b   = blockIdx.z;

#if HAS_TC
    const uint32_t sbase = smem_u32(smem);
    if (wid == 0) {
        asm volatile("tcgen05.alloc.cta_group::1.sync.aligned.shared::cta.b32 [%0], %1;"
                     :: "r"(sbase), "r"(256u) : "memory");
    }
    if (tid == 0)
        asm volatile("mbarrier.init.shared.b64 [%0], 1;" :: "r"(sbase + 8) : "memory");

    // ---- stage A (hi/lo) and B (hi/lo), SW128 ----
    {
        const __nv_bfloat16* asrc[2] = {g_ah, g_al};
        #pragma unroll
        for (int m = 0; m < 2; ++m) {
            const int abase = m ? SM_AL : SM_AH;
            #pragma unroll
            for (int sub = 0; sub < 2; ++sub)
                #pragma unroll
                for (int q = 0; q < 4; ++q) {
                    const int e = tid + q*256;        // 0..1023
                    const int row = e >> 3, u = e & 7;
                    cp16(smem + abase + sub*16384 + row*128 + ((u ^ (row & 7)) * 16),
                         &asrc[m][(it0 + row)*NN + kb + sub*64 + u*8]);
                }
        }
        const __nv_bfloat16* bsrc[2] = {g_bh, g_bl};
        #pragma unroll
        for (int m = 0; m < 2; ++m) {
            const int bbase = m ? SM_BL : SM_BH;
            #pragma unroll
            for (int sub = 0; sub < 2; ++sub)
                #pragma unroll
                for (int q = 0; q < 8; ++q) {
                    const int e = tid + q*256;        // 0..2047
                    const int row = e >> 3, u = e & 7;
                    cp16(smem + bbase + sub*32768 + row*128 + ((u ^ (row & 7)) * 16),
                         &bsrc[m][b*256*NN + row*NN + kb + sub*64 + u*8]);
                }
        }
    }
    cp_commit();
    cp_wait<0>();
    __syncthreads();
    asm volatile("fence.proxy.async.shared::cta;" ::: "memory");

    uint32_t tmem;
    asm volatile("ld.shared.b32 %0, [%1];" : "=r"(tmem) : "r"(sbase));

    if (wid == 0 && elect_one_pred()) {
        const u64 adh = make_desc(sbase + SM_AH), adl = make_desc(sbase + SM_AL);
        const u64 bdh = make_desc(sbase + SM_BH), bdl = make_desc(sbase + SM_BL);
        const u64 ad[3] = {adh, adh, adl};
        const u64 bd[3] = {bdh, bdl, bdh};
        int first = 1;
        #pragma unroll
        for (int sp = 0; sp < 3; ++sp)
            #pragma unroll
            for (int sub = 0; sub < 2; ++sub)
                #pragma unroll
                for (int ks = 0; ks < 4; ++ks) {
                    mma_f16_ss(tmem, ad[sp] + sub*1024 + ks*2,
                               bd[sp] + sub*2048 + ks*2, MMA_IDESC, first ? 0u : 1u);
                    first = 0;
                }
        asm volatile(
            "tcgen05.commit.cta_group::1.mbarrier::arrive::one.shared::cluster.b64 [%0];"
            :: "r"(sbase + 8) : "memory");
    }
    __syncthreads();
    {
        uint32_t done;
        asm volatile("{\n\t.reg .pred p;\n\t"
            "mbarrier.try_wait.parity.acquire.cta.shared::cta.b64 p, [%1], 0;\n\t"
            "selp.b32 %0, 1, 0, p;\n\t}" : "=r"(done) : "r"(sbase + 8) : "memory");
        if (!done) {
            asm volatile("{\n\t.reg .pred P1;\n\t"
                "WL_%=:\n\t"
                "mbarrier.try_wait.parity.acquire.cta.shared::cta.b64 P1, [%0], 0, 0x989680;\n\t"
                "@P1 bra.uni WD_%=;\n\tbra.uni WL_%=;\n\tWD_%=:\n\t}"
                :: "r"(sbase + 8) : "memory");
        }
    }
    asm volatile("tcgen05.fence::after_thread_sync;" ::: "memory");

    // ---- epilogue: 8 warps; warps 0-3 cols 0..127, warps 4-7 cols 128..255 ----
    {
        const int colbase = (wid >> 2) * 128;
        const int rowi = it0 + (wid & 3) * 32 + lane;
        float* dst = &g_part[(((size_t)blockIdx.y*BS + b)*NN + rowi) * 256 + colbase];
        for (int cb = 0; cb < 128; cb += 32) {
            uint32_t rg[32];
            TMEM_LD32(rg, tmem + colbase + cb);
            asm volatile("tcgen05.wait::ld.sync.aligned;" ::: "memory");
            #pragma unroll
            for (int t = 0; t < 8; ++t)
                *(float4*)&dst[cb + t*4] = make_float4(
                    __uint_as_float(rg[t*4+0]), __uint_as_float(rg[t*4+1]),
                    __uint_as_float(rg[t*4+2]), __uint_as_float(rg[t*4+3]));
        }
    }

    __syncthreads();
    if (tid == 0)
        asm volatile("mbarrier.inval.shared.b64 [%0];" :: "r"(sbase + 8) : "memory");
    __syncthreads();
    if (wid == 0) {
        asm volatile("tcgen05.relinquish_alloc_permit.cta_group::1.sync.aligned;");
        asm volatile("tcgen05.dealloc.cta_group::1.sync.aligned.b32 %0, %1;"
                     :: "r"(tmem), "r"(256u));
    }
#else
    (void)smem; (void)wid; (void)lane;
    if (tid < 128) {
        const int i = it0 + tid;
        float* dst = &g_part[(((size_t)blockIdx.y*BS + b)*NN + i) * 256];
        for (int n = 0; n < 256; ++n) {
            float acc = 0.f;
            for (int jj = 0; jj < 128; ++jj) {
                const float a = __bfloat162float(g_ah[i*NN + kb + jj])
                              + __bfloat162float(g_al[i*NN + kb + jj]);
                const float bb = __bfloat162float(g_bh[b*256*NN + n*NN + kb + jj])
                               + __bfloat162float(g_bl[b*256*NN + n*NN + kb + jj]);
                acc += a * bb;
            }
            dst[n] = acc;
        }
    }
#endif
}

// ---------------- K4: reduce K-split partials + epilogue ----------------
__global__ __launch_bounds__(256) void reduce_kernel(float* __restrict__ out)
{
    const int idx4 = (blockIdx.x * 256 + threadIdx.x) * 4;
    const int b = idx4 >> 16;
    const int i = (idx4 >> 7) & (NN - 1);
    const int d = idx4 & (DD - 1);

    float4 n = make_float4(0.f, 0.f, 0.f, 0.f);
    float4 dn = make_float4(0.f, 0.f, 0.f, 0.f);
    #pragma unroll
    for (int ks = 0; ks < KS; ++ks) {
        const float* base = &g_part[(((size_t)ks*BS + b)*NN + i) * 256];
        const float4 a = *(const float4*)&base[d];
        const float4 c = *(const float4*)&base[128 + d];
        n.x += a.x; n.y += a.y; n.z += a.z; n.w += a.w;
        dn.x += c.x; dn.y += c.y; dn.z += c.z; dn.w += c.w;
    }
    const float4 sq = *(const float4*)&g_sq[idx4];
    float4 o;
    o.x = sq.x * __fdividef(n.x, dn.x);
    o.y = sq.y * __fdividef(n.y, dn.y);
    o.z = sq.z * __fdividef(n.z, dn.z);
    o.w = sq.w * __fdividef(n.w, dn.w);
    *(float4*)&out[idx4] = o;
}

// ---------------- launch ----------------
extern "C" void kernel_launch(void* const* d_in, const int* in_sizes, int n_in,
                              void* d_out, int out_size)
{
    const float* x  = (const float*)d_in[0];
    const float* Wq = (const float*)d_in[1];
    const float* bq = (const float*)d_in[2];
    const float* Wk = (const float*)d_in[3];
    const float* bk = (const float*)d_in[4];
    const float* Wv = (const float*)d_in[5];
    const float* bv = (const float*)d_in[6];
    const float* B  = (const float*)d_in[7];
    float* out = (float*)d_out;

    const int proj_smem = (2048 + 128*128) * sizeof(float);   // 72KB
    cudaFuncSetAttribute(proj_kernel, cudaFuncAttributeMaxDynamicSharedMemorySize, proj_smem);
    cudaFuncSetAttribute(aft_tc_kernel, cudaFuncAttributeMaxDynamicSharedMemorySize, SM_TOTAL);

    proj_kernel<<<dim3(64, 4), 256, proj_smem>>>(x, Wq, bq, Wk, bk, Wv, bv, B);
    convert_kernel<<<dim3(16, 4, 2), 256>>>();
    aft_tc_kernel<<<dim3(4, KS, BS), 256, SM_TOTAL>>>();
    reduce_kernel<<<SZ/4/256, 256>>>(out);
}

// round 15
// speedup vs baseline: 1.6473x; 1.0809x over previous
#include <cuda_runtime.h>
#include <cuda_bf16.h>
#include <cstdint>

#define BS 2
#define NN 512
#define DD 128
#define SZ (BS*NN*DD)   // 131072
#define KS 4            // K-splits in tensor GEMM

#if defined(__CUDA_ARCH_FEAT_SM103_ALL) || defined(__CUDA_ARCH_FEAT_SM100_ALL) || defined(__CUDA_ARCH_FEAT_SM101_ALL)
#define HAS_TC 1
#else
#define HAS_TC 0
#endif

typedef unsigned long long u64;

// ---------------- device scratch ----------------
__device__ float g_sq[SZ];                    // sigmoid(q)
__device__ float g_ek[SZ];                    // exp(k) f32
__device__ float g_v [SZ];                    // raw v f32
__device__ __nv_bfloat16 g_ah[NN*NN];         // eB hi
__device__ __nv_bfloat16 g_al[NN*NN];         // eB lo
__device__ __nv_bfloat16 g_bh[BS*256*NN];     // [b][n][j]: n<128 ev^T, n>=128 ek^T (hi)
__device__ __nv_bfloat16 g_bl[BS*256*NN];     // lo
__device__ float g_part[KS*BS*NN*256];        // MMA partials [ks][b][i][256]

// ---------------- helpers ----------------
__device__ __forceinline__ u64 pack2(float lo, float hi) {
    u64 r; asm("mov.b64 %0, {%1, %2};" : "=l"(r) : "f"(lo), "f"(hi)); return r;
}
__device__ __forceinline__ void ffma2(u64 &acc, u64 a, u64 b) {
    asm("fma.rn.f32x2 %0, %1, %2, %0;" : "+l"(acc) : "l"(a), "l"(b));
}
__device__ __forceinline__ float2 unpack2(u64 v) {
    float lo, hi; asm("mov.b64 {%0, %1}, %2;" : "=f"(lo), "=f"(hi) : "l"(v));
    return make_float2(lo, hi);
}
__device__ __forceinline__ void cp16(void* sdst, const void* gsrc) {
    unsigned s = (unsigned)__cvta_generic_to_shared(sdst);
    asm volatile("cp.async.ca.shared.global [%0], [%1], 16;" :: "r"(s), "l"(gsrc));
}
__device__ __forceinline__ void cp_commit() { asm volatile("cp.async.commit_group;"); }
template<int NPEND> __device__ __forceinline__ void cp_wait() {
    asm volatile("cp.async.wait_group %0;" :: "n"(NPEND));
}
__device__ __forceinline__ uint32_t smem_u32(const void* p) {
    return (uint32_t)__cvta_generic_to_shared(p);
}
__device__ __forceinline__ void bf16_split(float v, __nv_bfloat16& h, __nv_bfloat16& l) {
    h = __float2bfloat16(v);
    l = __float2bfloat16(v - __bfloat162float(h));
}

#if HAS_TC
__device__ __forceinline__ uint32_t elect_one_pred() {
    uint32_t pred;
    asm volatile("{\n\t.reg .pred p;\n\telect.sync _|p, 0xFFFFFFFF;\n\t"
                 "selp.b32 %0, 1, 0, p;\n\t}" : "=r"(pred));
    return pred;
}
static constexpr u64 DESC_BASE_SW128 =
    (u64(2) << 61) | (u64(1) << 46) | (u64(64) << 32) | (u64(1) << 16);
__device__ __forceinline__ u64 make_desc(uint32_t addr) {
    return DESC_BASE_SW128 | ((u64)(addr >> 4) & 0x3FFF);
}
__device__ __forceinline__ void mma_f16_ss(uint32_t d_tmem, u64 a_desc, u64 b_desc,
                                           uint32_t idesc, uint32_t en) {
    asm volatile(
        "{\n\t.reg .pred p;\n\tsetp.ne.u32 p, %5, 0;\n\t"
        "tcgen05.mma.cta_group::1.kind::f16 [%0], %1, %2, %3, {%4, %4, %4, %4}, p;\n\t}"
        :: "r"(d_tmem), "l"(a_desc), "l"(b_desc), "r"(idesc), "r"(0u), "r"(en)
        : "memory");
}
static constexpr uint32_t MMA_IDESC =
    (1u << 4) | (1u << 7) | (1u << 10) | ((256u/8) << 17) | ((128u/16) << 24);
#define TMEM_LD32(r, addr) \
    asm volatile( \
        "tcgen05.ld.sync.aligned.32x32b.x32.b32 " \
        "{%0, %1, %2, %3, %4, %5, %6, %7, %8, %9, %10, %11, %12, %13, %14, %15, " \
        " %16, %17, %18, %19, %20, %21, %22, %23, %24, %25, %26, %27, %28, %29, %30, %31}, [%32];" \
        : "=r"((r)[0]), "=r"((r)[1]), "=r"((r)[2]), "=r"((r)[3]), "=r"((r)[4]), "=r"((r)[5]), \
          "=r"((r)[6]), "=r"((r)[7]), "=r"((r)[8]), "=r"((r)[9]), "=r"((r)[10]), "=r"((r)[11]), \
          "=r"((r)[12]), "=r"((r)[13]), "=r"((r)[14]), "=r"((r)[15]), "=r"((r)[16]), "=r"((r)[17]), \
          "=r"((r)[18]), "=r"((r)[19]), "=r"((r)[20]), "=r"((r)[21]), "=r"((r)[22]), "=r"((r)[23]), \
          "=r"((r)[24]), "=r"((r)[25]), "=r"((r)[26]), "=r"((r)[27]), "=r"((r)[28]), "=r"((r)[29]), \
          "=r"((r)[30]), "=r"((r)[31]) : "r"(addr))
#endif

// ---------------- K1: q/k/v projections + eB bf16 hi/lo (R7/R12 form) ----------------
// grid (64, 4), 256 threads.
__global__ __launch_bounds__(256) void proj_kernel(
    const float* __restrict__ x,
    const float* __restrict__ Wq, const float* __restrict__ bq,
    const float* __restrict__ Wk, const float* __restrict__ bk,
    const float* __restrict__ Wv, const float* __restrict__ bv,
    const float* __restrict__ Bm)
{
    __shared__ float xs[16*128];
    __shared__ float Ws[2][32*128];
    const int mat = blockIdx.y;
    const int tid = threadIdx.x;

    if (mat == 3) {
        #pragma unroll
        for (int r = 0; r < 4; ++r) {
            const int off = blockIdx.x * 4096 + r * 1024 + tid * 4;
            const float4 b4 = *(const float4*)&Bm[off];
            float e[4] = {__expf(b4.x), __expf(b4.y), __expf(b4.z), __expf(b4.w)};
            __nv_bfloat16 h[4], l[4];
            #pragma unroll
            for (int t = 0; t < 4; ++t) bf16_split(e[t], h[t], l[t]);
            *(uint2*)&g_ah[off] = *(uint2*)h;
            *(uint2*)&g_al[off] = *(uint2*)l;
        }
        return;
    }

    const float* W    = (mat==0) ? Wq : ((mat==1) ? Wk : Wv);
    const float* bias = (mat==0) ? bq : ((mat==1) ? bk : bv);
    const int row0 = blockIdx.x * 16;
    const int dt = tid & 31, rt = tid >> 5;
    const int d = dt * 4;

    for (int q = tid; q < 16*128/4; q += 256) cp16(&xs[q*4], &x[row0*128 + q*4]);
    for (int q = tid; q < 32*128/4; q += 256) cp16(&Ws[0][q*4], &W[q*4]);
    cp_commit();

    const float4 bb = *(const float4*)&bias[d];
    u64 a00 = pack2(bb.x, bb.y), a01 = pack2(bb.z, bb.w);
    u64 a10 = a00, a11 = a01;

    for (int cc = 0; cc < 128; cc += 32) {
        const int s = (cc >> 5) & 1;
        if (cc + 32 < 128) {
            const int sn = s ^ 1;
            const float* Wn = &W[(cc + 32) * 128];
            for (int q = tid; q < 32*128/4; q += 256) cp16(&Ws[sn][q*4], &Wn[q*4]);
            cp_commit();
            cp_wait<1>();
        } else {
            cp_wait<0>();
        }
        __syncthreads();
        #pragma unroll
        for (int c = 0; c < 32; ++c) {
            const u64* wrow = (const u64*)&Ws[s][c*128 + d];
            const u64 w01 = wrow[0], w23 = wrow[1];
            const float x0 = xs[rt*128 + cc + c];
            const float x1 = xs[(rt+8)*128 + cc + c];
            const u64 X0 = pack2(x0, x0), X1 = pack2(x1, x1);
            ffma2(a00, X0, w01); ffma2(a01, X0, w23);
            ffma2(a10, X1, w01); ffma2(a11, X1, w23);
        }
        __syncthreads();
    }

    #pragma unroll
    for (int r = 0; r < 2; ++r) {
        const int grow = row0 + ((r == 0) ? rt : (rt + 8));
        const float2 p = unpack2(r ? a10 : a00);
        const float2 q2 = unpack2(r ? a11 : a01);
        float4 o = make_float4(p.x, p.y, q2.x, q2.y);
        if (mat == 0) {
            o.x = 1.f/(1.f+__expf(-o.x)); o.y = 1.f/(1.f+__expf(-o.y));
            o.z = 1.f/(1.f+__expf(-o.z)); o.w = 1.f/(1.f+__expf(-o.w));
            *(float4*)&g_sq[grow*128 + d] = o;
        } else if (mat == 1) {
            o.x = __expf(o.x); o.y = __expf(o.y);
            o.z = __expf(o.z); o.w = __expf(o.w);
            *(float4*)&g_ek[grow*128 + d] = o;
        } else {
            *(float4*)&g_v[grow*128 + d] = o;
        }
    }
}

// ---------------- K2: transpose + bf16 hi/lo split of ek / ev ----------------
// grid (16, 4, 2): 32-j tile, 32-d tile, batch. 256 threads.
__global__ __launch_bounds__(256) void convert_kernel()
{
    __shared__ float ekS[32][33], vS[32][33];
    const int j0 = blockIdx.x * 32;
    const int d0 = blockIdx.y * 32;
    const int b  = blockIdx.z;
    const int tid = threadIdx.x;
    const int lane = tid & 31, rw = tid >> 5;

    #pragma unroll
    for (int p = 0; p < 4; ++p) {
        const int r = rw + p*8;
        ekS[r][lane] = g_ek[(b*NN + j0 + r)*DD + d0 + lane];
        vS [r][lane] = g_v [(b*NN + j0 + r)*DD + d0 + lane];
    }
    __syncthreads();

    #pragma unroll
    for (int p = 0; p < 4; ++p) {
        const int r = rw + p*8;
        const float ek = ekS[lane][r];
        const float ev = ek * vS[lane][r];
        __nv_bfloat16 evh, evl, ekh, ekl;
        bf16_split(ev, evh, evl);
        bf16_split(ek, ekh, ekl);
        const int offv = b*256*NN + (d0 + r)*NN + j0 + lane;
        const int offk = b*256*NN + (128 + d0 + r)*NN + j0 + lane;
        g_bh[offv] = evh; g_bl[offv] = evl;
        g_bh[offk] = ekh; g_bl[offk] = ekl;
    }
}

// ---------------- K3: tcgen05 GEMM  part = eB @ [ev|ek]  (bf16-split x3, R12 form) ----------------
#define SM_AH 1024
#define SM_AL (SM_AH + 32768)
#define SM_BH (SM_AL + 32768)
#define SM_BL (SM_BH + 65536)
#define SM_TOTAL (SM_BL + 65536 + 1024)

__global__ __launch_bounds__(128) void aft_tc_kernel()
{
    extern __shared__ char smem[];
    const int tid = threadIdx.x;
    const int wid = tid >> 5, lane = tid & 31;
    const int it0 = blockIdx.x * 128;
    const int kb  = blockIdx.y * 128;
    const int b   = blockIdx.z;

#if HAS_TC
    const uint32_t sbase = smem_u32(smem);
    if (wid == 0) {
        asm volatile("tcgen05.alloc.cta_group::1.sync.aligned.shared::cta.b32 [%0], %1;"
                     :: "r"(sbase), "r"(256u) : "memory");
    }
    if (tid == 0)
        asm volatile("mbarrier.init.shared.b64 [%0], 1;" :: "r"(sbase + 8) : "memory");

    {
        const __nv_bfloat16* asrc[2] = {g_ah, g_al};
        #pragma unroll
        for (int m = 0; m < 2; ++m) {
            const int abase = m ? SM_AL : SM_AH;
            #pragma unroll
            for (int sub = 0; sub < 2; ++sub)
                #pragma unroll
                for (int q = 0; q < 8; ++q) {
                    const int e = tid + q*128;
                    const int row = e >> 3, u = e & 7;
                    cp16(smem + abase + sub*16384 + row*128 + ((u ^ (row & 7)) * 16),
                         &asrc[m][(it0 + row)*NN + kb + sub*64 + u*8]);
                }
        }
        const __nv_bfloat16* bsrc[2] = {g_bh, g_bl};
        #pragma unroll
        for (int m = 0; m < 2; ++m) {
            const int bbase = m ? SM_BL : SM_BH;
            #pragma unroll
            for (int sub = 0; sub < 2; ++sub)
                #pragma unroll
                for (int q = 0; q < 16; ++q) {
                    const int e = tid + q*128;
                    const int row = e >> 3, u = e & 7;
                    cp16(smem + bbase + sub*32768 + row*128 + ((u ^ (row & 7)) * 16),
                         &bsrc[m][b*256*NN + row*NN + kb + sub*64 + u*8]);
                }
        }
    }
    cp_commit();
    cp_wait<0>();
    __syncthreads();
    asm volatile("fence.proxy.async.shared::cta;" ::: "memory");

    uint32_t tmem;
    asm volatile("ld.shared.b32 %0, [%1];" : "=r"(tmem) : "r"(sbase));

    if (wid == 0 && elect_one_pred()) {
        const u64 adh = make_desc(sbase + SM_AH), adl = make_desc(sbase + SM_AL);
        const u64 bdh = make_desc(sbase + SM_BH), bdl = make_desc(sbase + SM_BL);
        const u64 ad[3] = {adh, adh, adl};
        const u64 bd[3] = {bdh, bdl, bdh};
        int first = 1;
        #pragma unroll
        for (int sp = 0; sp < 3; ++sp)
            #pragma unroll
            for (int sub = 0; sub < 2; ++sub)
                #pragma unroll
                for (int ks = 0; ks < 4; ++ks) {
                    mma_f16_ss(tmem, ad[sp] + sub*1024 + ks*2,
                               bd[sp] + sub*2048 + ks*2, MMA_IDESC, first ? 0u : 1u);
                    first = 0;
                }
        asm volatile(
            "tcgen05.commit.cta_group::1.mbarrier::arrive::one.shared::cluster.b64 [%0];"
            :: "r"(sbase + 8) : "memory");
    }
    __syncthreads();
    {
        uint32_t done;
        asm volatile("{\n\t.reg .pred p;\n\t"
            "mbarrier.try_wait.parity.acquire.cta.shared::cta.b64 p, [%1], 0;\n\t"
            "selp.b32 %0, 1, 0, p;\n\t}" : "=r"(done) : "r"(sbase + 8) : "memory");
        if (!done) {
            asm volatile("{\n\t.reg .pred P1;\n\t"
                "WL_%=:\n\t"
                "mbarrier.try_wait.parity.acquire.cta.shared::cta.b64 P1, [%0], 0, 0x989680;\n\t"
                "@P1 bra.uni WD_%=;\n\tbra.uni WL_%=;\n\tWD_%=:\n\t}"
                :: "r"(sbase + 8) : "memory");
        }
    }
    asm volatile("tcgen05.fence::after_thread_sync;" ::: "memory");

    float* dst = &g_part[(((size_t)blockIdx.y*BS + b)*NN + it0 + wid*32 + lane) * 256];
    for (int cb = 0; cb < 256; cb += 32) {
        uint32_t rg[32];
        TMEM_LD32(rg, tmem + cb);
        asm volatile("tcgen05.wait::ld.sync.aligned;" ::: "memory");
        #pragma unroll
        for (int t = 0; t < 8; ++t)
            *(float4*)&dst[cb + t*4] = make_float4(
                __uint_as_float(rg[t*4+0]), __uint_as_float(rg[t*4+1]),
                __uint_as_float(rg[t*4+2]), __uint_as_float(rg[t*4+3]));
    }

    __syncthreads();
    if (tid == 0)
        asm volatile("mbarrier.inval.shared.b64 [%0];" :: "r"(sbase + 8) : "memory");
    __syncthreads();
    if (wid == 0) {
        asm volatile("tcgen05.relinquish_alloc_permit.cta_group::1.sync.aligned;");
        asm volatile("tcgen05.dealloc.cta_group::1.sync.aligned.b32 %0, %1;"
                     :: "r"(tmem), "r"(256u));
    }
#else
    (void)smem; (void)wid; (void)lane;
    const int i = it0 + tid;
    float* dst = &g_part[(((size_t)blockIdx.y*BS + b)*NN + i) * 256];
    for (int n = 0; n < 256; ++n) {
        float acc = 0.f;
        for (int jj = 0; jj < 128; ++jj) {
            const float a = __bfloat162float(g_ah[i*NN + kb + jj])
                          + __bfloat162float(g_al[i*NN + kb + jj]);
            const float bb = __bfloat162float(g_bh[b*256*NN + n*NN + kb + jj])
                           + __bfloat162float(g_bl[b*256*NN + n*NN + kb + jj]);
            acc += a * bb;
        }
        dst[n] = acc;
    }
#endif
}

// ---------------- K4: reduce — fine-grained, MLP-9, 4x occupancy ----------------
// 512 blocks x 256 threads, ONE output float per thread; 9 independent loads.
__global__ __launch_bounds__(256) void reduce_kernel(float* __restrict__ out)
{
    const int idx = blockIdx.x * 256 + threadIdx.x;   // 0..131071
    const int b = idx >> 16;
    const int i = (idx >> 7) & (NN - 1);
    const int d = idx & (DD - 1);

    const int base0 = ((b)*NN + i) * 256;
    // 8 independent partial loads (4 num + 4 den), all in flight together
    float n0, n1, n2, n3, d0, d1, d2, d3;
    {
        const float* p0 = &g_part[base0];
        const float* p1 = &g_part[(size_t)(1*BS)*NN*256 + base0];
        const float* p2 = &g_part[(size_t)(2*BS)*NN*256 + base0];
        const float* p3 = &g_part[(size_t)(3*BS)*NN*256 + base0];
        n0 = p0[d];       n1 = p1[d];       n2 = p2[d];       n3 = p3[d];
        d0 = p0[128 + d]; d1 = p1[128 + d]; d2 = p2[128 + d]; d3 = p3[128 + d];
    }
    const float sq = g_sq[idx];
    const float num = (n0 + n1) + (n2 + n3);
    const float den = (d0 + d1) + (d2 + d3);
    out[idx] = sq * __fdividef(num, den);
}

// ---------------- launch ----------------
extern "C" void kernel_launch(void* const* d_in, const int* in_sizes, int n_in,
                              void* d_out, int out_size)
{
    const float* x  = (const float*)d_in[0];
    const float* Wq = (const float*)d_in[1];
    const float* bq = (const float*)d_in[2];
    const float* Wk = (const float*)d_in[3];
    const float* bk = (const float*)d_in[4];
    const float* Wv = (const float*)d_in[5];
    const float* bv = (const float*)d_in[6];
    const float* B  = (const float*)d_in[7];
    float* out = (float*)d_out;

    cudaFuncSetAttribute(aft_tc_kernel, cudaFuncAttributeMaxDynamicSharedMemorySize, SM_TOTAL);

    proj_kernel<<<dim3(64, 4), 256>>>(x, Wq, bq, Wk, bk, Wv, bv, B);
    convert_kernel<<<dim3(16, 4, 2), 256>>>();
    aft_tc_kernel<<<dim3(4, KS, BS), 128, SM_TOTAL>>>();
    reduce_kernel<<<512, 256>>>(out);
}